// round 16
// baseline (speedup 1.0000x reference)
#include <cuda_runtime.h>

#define NB 128
#define THREADS 512
#define NITER 60
#define TS 132

// float offsets into dynamic smem (per CTA)
#define OFF_W    0                      // w[128][128]        16384
#define OFF_RT   16384                  // rowtab[32*TS]       4224
#define OFF_CT   20608                  // coltab[16*TS]       2112
#define OFF_SY   22720                  // sy[128]
#define OFF_SORT 22848                  // sorted[128]
#define OFF_CSUM 22976                  // csum[2][128]
#define OFF_RANK 23232                  // int rankp[4][128]
#define OFF_WS   23744                  // wsum[4], wcnt[4]
#define SMEM_FLOATS 23752               // ~92.8 KB

typedef unsigned long long ull;

__device__ __forceinline__ ull pk2(float lo, float hi) {
    ull r; asm("mov.b64 %0, {%1, %2};" : "=l"(r) : "f"(lo), "f"(hi)); return r;
}
__device__ __forceinline__ void upk2(ull v, float& lo, float& hi) {
    asm("mov.b64 {%0, %1}, %2;" : "=f"(lo), "=f"(hi) : "l"(v));
}
__device__ __forceinline__ ull padd2(ull a, ull b) {
    ull r; asm("add.rn.f32x2 %0, %1, %2;" : "=l"(r) : "l"(a), "l"(b)); return r;
}
__device__ __forceinline__ ull psub2(ull a, ull b) {
    ull r; asm("sub.rn.f32x2 %0, %1, %2;" : "=l"(r) : "l"(a), "l"(b)); return r;
}

extern __shared__ float smf[];

__global__ void __launch_bounds__(THREADS, 2)
gfusedmax_kernel(const float* __restrict__ x,
                 const float* __restrict__ A,
                 float* __restrict__ out)
{
    const int b     = blockIdx.x;
    const int tid   = threadIdx.x;
    const int lane  = tid & 31;
    const int warp  = tid >> 5;            // 16 warps; warp w owns rows 8w..8w+7
    const float step = 1.0f / 256.0f;      // lane L owns cols 4L..4L+3

    // ---- stream this problem's clip bounds into smem (coalesced float4) ----
    {
        float4* wdst = reinterpret_cast<float4*>(smf + OFF_W);
        const float4* wsrc = reinterpret_cast<const float4*>(A + (size_t)b * NB * NB);
        #pragma unroll
        for (int i = 0; i < 8; ++i)        // 16384 floats = 4096 float4
            wdst[tid + i * 512] = wsrc[tid + i * 512];
    }

    // ---- z state: 8 rows x 4 cols packed, init 0 ----
    ull z2[8][2];
    #pragma unroll
    for (int r = 0; r < 8; ++r) { z2[r][0] = 0ULL; z2[r][1] = 0ULL; }

    // ---- phase-B identity: j0 = tid>>3 in [0,64), also handles j1 = j0+64 ----
    const int j0 = tid >> 3;
    const int g  = tid & 7;
    const int j1 = j0 + 64;
    const float xq0 = x[(size_t)b * NB + j0];
    const float xq1 = x[(size_t)b * NB + j1];

    // pointers
    const float* wp  = smf + OFF_W + warp * (8 * NB) + 4 * lane;   // + r*128 per row
    float* rtw = smf + OFF_RT + lane * TS + 8 * warp;              // rowtab[lane][8w+r]
    float* ctw = smf + OFF_CT + warp * TS + 4 * lane;              // coltab[warp][4L..]
    const float* rrd = smf + OFF_RT + g * TS;                      // + 8k*TS + j
    const float* crd = smf + OFF_CT + g * TS;                      // + 8k*TS + j
    float* syp = smf + OFF_SY;

    if (g == 0) { syp[j0] = step * xq0; syp[j1] = step * xq1; }
    __syncthreads();

    // ---- 60 projected-gradient iterations, 2 bars each (hidden by 2 CTAs/SM) ----
    #pragma unroll 1
    for (int it = 0; it < NITER; ++it) {
        // ===== phase A =====
        float4 sc4 = *reinterpret_cast<const float4*>(syp + 4 * lane);   // cols
        float4 sra = *reinterpret_cast<const float4*>(syp + 8 * warp);   // rows 8w..8w+3
        float4 srb = *reinterpret_cast<const float4*>(syp + 8 * warp + 4);
        ull c2_0 = pk2(sc4.x, sc4.y);
        ull c2_1 = pk2(sc4.z, sc4.w);
        const float syr[8] = {sra.x, sra.y, sra.z, sra.w, srb.x, srb.y, srb.z, srb.w};

        ull ca0, ca1;
        float4 rva, rvb;
        float* rvap = &rva.x;
        float* rvbp = &rvb.x;

        // distance-1 prefetch of w rows through the unrolled loop
        float4 wr_cur = *reinterpret_cast<const float4*>(wp);

        #pragma unroll
        for (int r = 0; r < 8; ++r) {
            float4 wr_nxt = (r < 7)
                ? *reinterpret_cast<const float4*>(wp + (r + 1) * NB)
                : wr_cur;
            float4 wr = wr_cur;

            ull s2 = pk2(syr[r], syr[r]);
            // cols (4L, 4L+1)
            ull v0 = padd2(z2[r][0], psub2(s2, c2_0));
            float ax, ay; upk2(v0, ax, ay);
            ax = fminf(fmaxf(ax, -wr.x), wr.x);
            ay = fminf(fmaxf(ay, -wr.y), wr.y);
            ull zz0 = pk2(ax, ay);
            z2[r][0] = zz0;
            // cols (4L+2, 4L+3)
            ull v1 = padd2(z2[r][1], psub2(s2, c2_1));
            float bx, by; upk2(v1, bx, by);
            bx = fminf(fmaxf(bx, -wr.z), wr.z);
            by = fminf(fmaxf(by, -wr.w), wr.w);
            ull zz1 = pk2(bx, by);
            z2[r][1] = zz1;
            // accumulate
            if (r == 0) { ca0 = zz0; ca1 = zz1; }
            else        { ca0 = padd2(ca0, zz0); ca1 = padd2(ca1, zz1); }
            ull rs2 = padd2(zz0, zz1);
            float rl, rh; upk2(rs2, rl, rh);
            if (r < 4) rvap[r] = rl + rh; else rvbp[r - 4] = rl + rh;

            wr_cur = wr_nxt;
        }

        // packed partial stores (quarter-warp conflict-free)
        *reinterpret_cast<float4*>(rtw)     = rva;
        *reinterpret_cast<float4*>(rtw + 4) = rvb;
        {
            float4 cv;
            upk2(ca0, cv.x, cv.y);
            upk2(ca1, cv.z, cv.w);
            *reinterpret_cast<float4*>(ctw) = cv;
        }
        __syncthreads();

        // ===== phase B: 8 threads per j, each thread covers j0 and j1 =====
        float r00 = rrd[0 * 8 * TS + j0], r01 = rrd[1 * 8 * TS + j0];
        float r02 = rrd[2 * 8 * TS + j0], r03 = rrd[3 * 8 * TS + j0];
        float c00 = crd[0 * 8 * TS + j0], c01 = crd[1 * 8 * TS + j0];
        float r10 = rrd[0 * 8 * TS + j1], r11 = rrd[1 * 8 * TS + j1];
        float r12 = rrd[2 * 8 * TS + j1], r13 = rrd[3 * 8 * TS + j1];
        float c10 = crd[0 * 8 * TS + j1], c11 = crd[1 * 8 * TS + j1];
        float d0 = (c00 + c01) - ((r00 + r01) + (r02 + r03));
        float d1 = (c10 + c11) - ((r10 + r11) + (r12 + r13));
        d0 += __shfl_xor_sync(0xffffffffu, d0, 1);
        d1 += __shfl_xor_sync(0xffffffffu, d1, 1);
        d0 += __shfl_xor_sync(0xffffffffu, d0, 2);
        d1 += __shfl_xor_sync(0xffffffffu, d1, 2);
        d0 += __shfl_xor_sync(0xffffffffu, d0, 4);
        d1 += __shfl_xor_sync(0xffffffffu, d1, 4);
        if (g == 0) {
            syp[j0] = step * (xq0 + d0);
            syp[j1] = step * (xq1 + d1);
        }
        __syncthreads();
    }

    // ================= tail: sparsemax (512 threads, one problem) =============
    float* sortP = smf + OFF_SORT;
    float* csumP = smf + OFF_CSUM;
    int*   rankP = reinterpret_cast<int*>(smf + OFF_RANK);
    float* wsP   = smf + OFF_WS;
    float* wcP   = smf + OFF_WS + 4;

    // rank sort: 4 groups x 32 comparisons (branch-free, deterministic)
    {
        int i  = tid & 127;
        int gg = tid >> 7;                 // 0..3
        float vi = syp[i];
        int rp = 0;
        #pragma unroll
        for (int jj = 0; jj < 32; ++jj) {
            int jc = gg * 32 + jj;
            float uj = syp[jc];
            rp += (uj > vi) || (uj == vi && jc < i);
        }
        rankP[gg * NB + i] = rp;
    }
    __syncthreads();
    float yv = 0.0f;
    if (tid < NB) {
        yv = syp[tid] * 256.0f;            // exact (exponent-only)
        int rank = (rankP[tid] + rankP[NB + tid]) + (rankP[2 * NB + tid] + rankP[3 * NB + tid]);
        sortP[rank] = yv;                  // descending
    }
    __syncthreads();

    // inclusive scan (Hillis-Steele, ping-pong)
    if (tid < NB) csumP[tid] = sortP[tid];
    __syncthreads();
    int src = 0;
    for (int off = 1; off < NB; off <<= 1) {
        if (tid < NB) {
            float vv = csumP[src * NB + tid];
            if (tid >= off) vv += csumP[src * NB + tid - off];
            csumP[(1 - src) * NB + tid] = vv;
        }
        __syncthreads();
        src = 1 - src;
    }

    // mask + deterministic (sum, count) funnel (warps 0-3)
    if (tid < NB) {
        float s  = sortP[tid];
        float cu = csumP[src * NB + tid];
        float k  = (float)(tid + 1);
        bool  m  = (1.0f + k * s > cu);
        float sv = m ? s : 0.0f;
        float sc = m ? 1.0f : 0.0f;
        #pragma unroll
        for (int sft = 16; sft > 0; sft >>= 1) {
            sv += __shfl_xor_sync(0xffffffffu, sv, sft);
            sc += __shfl_xor_sync(0xffffffffu, sc, sft);
        }
        if (lane == 0) { wsP[tid >> 5] = sv; wcP[tid >> 5] = sc; }
    }
    __syncthreads();

    if (tid < NB) {
        float ssum = (wsP[0] + wsP[1]) + (wsP[2] + wsP[3]);
        float scnt = (wcP[0] + wcP[1]) + (wcP[2] + wcP[3]);
        float tau  = (ssum - 1.0f) / scnt;
        out[(size_t)b * NB + tid] = fmaxf(yv - tau, 0.0f);
    }
}

extern "C" void kernel_launch(void* const* d_in, const int* in_sizes, int n_in,
                              void* d_out, int out_size)
{
    const float* x = (const float*)d_in[0];   // [B, 128]
    const float* A = (const float*)d_in[1];   // [B, 128, 128]
    float* out = (float*)d_out;               // [B, 128] float32

    int B = in_sizes[0] / NB;                 // 4096
    size_t smem_bytes = (size_t)SMEM_FLOATS * sizeof(float);   // ~92.8 KB
    cudaFuncSetAttribute(gfusedmax_kernel,
                         cudaFuncAttributeMaxDynamicSharedMemorySize, (int)smem_bytes);
    gfusedmax_kernel<<<B, THREADS, smem_bytes>>>(x, A, out);
}

// round 17
// speedup vs baseline: 1.0359x; 1.0359x over previous
#include <cuda_runtime.h>

#define NB 128
#define THREADS 512
#define NITER 60
#define TS_R 129                        // rowtab stride (129 % 32 == 1)
#define TS_C 162                        // coltab stride (162 % 32 == 2)

// float offsets into dynamic smem (per CTA)
#define OFF_W    0                      // w[128][128]          16384
#define OFF_RT   16384                  // rowtab[32*129]        4128
#define OFF_CT   20512                  // coltab[32*162]        5184
#define OFF_SY   25696                  // sy[128]
#define OFF_SORT 25824                  // sorted[128]
#define OFF_CSUM 25952                  // csum[2][128]
#define OFF_RANK 26208                  // int rankp[4][128]
#define OFF_WS   26720                  // wsum[4], wcnt[4]
#define SMEM_FLOATS 26728               // ~104.4 KB

typedef unsigned long long ull;

__device__ __forceinline__ ull pk2(float lo, float hi) {
    ull r; asm("mov.b64 %0, {%1, %2};" : "=l"(r) : "f"(lo), "f"(hi)); return r;
}
__device__ __forceinline__ void upk2(ull v, float& lo, float& hi) {
    asm("mov.b64 {%0, %1}, %2;" : "=f"(lo), "=f"(hi) : "l"(v));
}
__device__ __forceinline__ ull padd2(ull a, ull b) {
    ull r; asm("add.rn.f32x2 %0, %1, %2;" : "=l"(r) : "l"(a), "l"(b)); return r;
}
__device__ __forceinline__ ull psub2(ull a, ull b) {
    ull r; asm("sub.rn.f32x2 %0, %1, %2;" : "=l"(r) : "l"(a), "l"(b)); return r;
}

extern __shared__ float smf[];

__global__ void __launch_bounds__(THREADS, 2)
gfusedmax_kernel(const float* __restrict__ x,
                 const float* __restrict__ A,
                 float* __restrict__ out)
{
    const int b     = blockIdx.x;
    const int tid   = threadIdx.x;
    const int lane  = tid & 31;
    const int warp  = tid >> 5;            // 16 warps; warp w owns rows 8w..8w+7
    const float step = 1.0f / 256.0f;      // lane L owns cols 4L..4L+3

    // ---- stream this problem's clip bounds into smem (coalesced float4) ----
    {
        float4* wdst = reinterpret_cast<float4*>(smf + OFF_W);
        const float4* wsrc = reinterpret_cast<const float4*>(A + (size_t)b * NB * NB);
        #pragma unroll
        for (int i = 0; i < 8; ++i)        // 16384 floats = 4096 float4
            wdst[tid + i * 512] = wsrc[tid + i * 512];
    }

    // ---- z state: 8 rows x 4 cols packed, init 0 ----
    ull z2[8][2];
    #pragma unroll
    for (int r = 0; r < 8; ++r) { z2[r][0] = 0ULL; z2[r][1] = 0ULL; }

    // ---- phase-B identity: 4 threads per j (adjacent lanes), j = tid>>2 ----
    const int j = tid >> 2;                // 0..127
    const int m = tid & 3;                 // contributor quarter
    const float xq = x[(size_t)b * NB + j];

    // pointers
    const float* wp  = smf + OFF_W + warp * (8 * NB) + 4 * lane;       // + r*128 per row
    float* rtw = smf + OFF_RT + lane * TS_R + 8 * warp;                // rowtab[lane][8w+r]
    float* ctw = smf + OFF_CT + warp * TS_C + 4 * lane + (lane >> 3);  // coltab[warp][swz(4L+c)]
    // B read bases: rowtab[8m+k][j] (k=0..7), coltab[4m+k'][swz(j)] (k'=0..3)
    const float* rrd = smf + OFF_RT + (8 * m) * TS_R + j;
    const float* crd = smf + OFF_CT + (4 * m) * TS_C + j + (j >> 5);
    float* syp = smf + OFF_SY;

    if (m == 0) syp[j] = step * xq;
    __syncthreads();

    // ---- 60 projected-gradient iterations, 2 bars each (hidden by 2 CTAs/SM) ----
    #pragma unroll 1
    for (int it = 0; it < NITER; ++it) {
        // ===== phase A =====
        float4 sc4 = *reinterpret_cast<const float4*>(syp + 4 * lane);   // cols
        float4 sra = *reinterpret_cast<const float4*>(syp + 8 * warp);   // rows 8w..8w+3
        float4 srb = *reinterpret_cast<const float4*>(syp + 8 * warp + 4);
        ull c2_0 = pk2(sc4.x, sc4.y);
        ull c2_1 = pk2(sc4.z, sc4.w);
        const float syr[8] = {sra.x, sra.y, sra.z, sra.w, srb.x, srb.y, srb.z, srb.w};

        ull ca0, ca1;

        #pragma unroll
        for (int r = 0; r < 8; ++r) {
            float4 wr = *reinterpret_cast<const float4*>(wp + r * NB);   // LDS.128
            ull s2 = pk2(syr[r], syr[r]);
            // cols (4L, 4L+1)
            ull v0 = padd2(z2[r][0], psub2(s2, c2_0));
            float ax, ay; upk2(v0, ax, ay);
            ax = fminf(fmaxf(ax, -wr.x), wr.x);
            ay = fminf(fmaxf(ay, -wr.y), wr.y);
            ull zz0 = pk2(ax, ay);
            z2[r][0] = zz0;
            // cols (4L+2, 4L+3)
            ull v1 = padd2(z2[r][1], psub2(s2, c2_1));
            float bx, by; upk2(v1, bx, by);
            bx = fminf(fmaxf(bx, -wr.z), wr.z);
            by = fminf(fmaxf(by, -wr.w), wr.w);
            ull zz1 = pk2(bx, by);
            z2[r][1] = zz1;
            // accumulate col sums
            if (r == 0) { ca0 = zz0; ca1 = zz1; }
            else        { ca0 = padd2(ca0, zz0); ca1 = padd2(ca1, zz1); }
            // row partial: scalar store, bank = lane + 8w + r -> conflict-free
            ull rs2 = padd2(zz0, zz1);
            float rl, rh; upk2(rs2, rl, rh);
            rtw[r] = rl + rh;
        }

        // col partials: scalar stores, bank = 2w + 4L + c + (L>>3) -> conflict-free
        {
            float c0v, c1v, c2v, c3v;
            upk2(ca0, c0v, c1v);
            upk2(ca1, c2v, c3v);
            ctw[0] = c0v; ctw[1] = c1v; ctw[2] = c2v; ctw[3] = c3v;
        }
        __syncthreads();

        // ===== phase B: 4 threads per j, 12 loads each, TWO shuffles =====
        float rs, cs;
        {
            float t0 = rrd[0 * TS_R] + rrd[1 * TS_R];
            float t1 = rrd[2 * TS_R] + rrd[3 * TS_R];
            float t2 = rrd[4 * TS_R] + rrd[5 * TS_R];
            float t3 = rrd[6 * TS_R] + rrd[7 * TS_R];
            rs = (t0 + t1) + (t2 + t3);
            float u0 = crd[0 * TS_C] + crd[1 * TS_C];
            float u1 = crd[2 * TS_C] + crd[3 * TS_C];
            cs = u0 + u1;
        }
        float d = cs - rs;
        d += __shfl_xor_sync(0xffffffffu, d, 1);
        d += __shfl_xor_sync(0xffffffffu, d, 2);
        if (m == 0) syp[j] = step * (xq + d);        // y = x - rowsum + colsum
        __syncthreads();
    }

    // ================= tail: sparsemax (512 threads, one problem) =============
    float* sortP = smf + OFF_SORT;
    float* csumP = smf + OFF_CSUM;
    int*   rankP = reinterpret_cast<int*>(smf + OFF_RANK);
    float* wsP   = smf + OFF_WS;
    float* wcP   = smf + OFF_WS + 4;

    // rank sort: 4 groups x 32 comparisons (branch-free, deterministic)
    {
        int i  = tid & 127;
        int gg = tid >> 7;                 // 0..3
        float vi = syp[i];
        int rp = 0;
        #pragma unroll
        for (int jj = 0; jj < 32; ++jj) {
            int jc = gg * 32 + jj;
            float uj = syp[jc];
            rp += (uj > vi) || (uj == vi && jc < i);
        }
        rankP[gg * NB + i] = rp;
    }
    __syncthreads();
    float yv = 0.0f;
    if (tid < NB) {
        yv = syp[tid] * 256.0f;            // exact (exponent-only)
        int rank = (rankP[tid] + rankP[NB + tid]) + (rankP[2 * NB + tid] + rankP[3 * NB + tid]);
        sortP[rank] = yv;                  // descending
    }
    __syncthreads();

    // inclusive scan (Hillis-Steele, ping-pong)
    if (tid < NB) csumP[tid] = sortP[tid];
    __syncthreads();
    int src = 0;
    for (int off = 1; off < NB; off <<= 1) {
        if (tid < NB) {
            float vv = csumP[src * NB + tid];
            if (tid >= off) vv += csumP[src * NB + tid - off];
            csumP[(1 - src) * NB + tid] = vv;
        }
        __syncthreads();
        src = 1 - src;
    }

    // mask + deterministic (sum, count) funnel (warps 0-3)
    if (tid < NB) {
        float s  = sortP[tid];
        float cu = csumP[src * NB + tid];
        float k  = (float)(tid + 1);
        bool  mm = (1.0f + k * s > cu);
        float sv = mm ? s : 0.0f;
        float sc = mm ? 1.0f : 0.0f;
        #pragma unroll
        for (int sft = 16; sft > 0; sft >>= 1) {
            sv += __shfl_xor_sync(0xffffffffu, sv, sft);
            sc += __shfl_xor_sync(0xffffffffu, sc, sft);
        }
        if (lane == 0) { wsP[tid >> 5] = sv; wcP[tid >> 5] = sc; }
    }
    __syncthreads();

    if (tid < NB) {
        float ssum = (wsP[0] + wsP[1]) + (wsP[2] + wsP[3]);
        float scnt = (wcP[0] + wcP[1]) + (wcP[2] + wcP[3]);
        float tau  = (ssum - 1.0f) / scnt;
        out[(size_t)b * NB + tid] = fmaxf(yv - tau, 0.0f);
    }
}

extern "C" void kernel_launch(void* const* d_in, const int* in_sizes, int n_in,
                              void* d_out, int out_size)
{
    const float* x = (const float*)d_in[0];   // [B, 128]
    const float* A = (const float*)d_in[1];   // [B, 128, 128]
    float* out = (float*)d_out;               // [B, 128] float32

    int B = in_sizes[0] / NB;                 // 4096
    size_t smem_bytes = (size_t)SMEM_FLOATS * sizeof(float);   // ~104.4 KB
    cudaFuncSetAttribute(gfusedmax_kernel,
                         cudaFuncAttributeMaxDynamicSharedMemorySize, (int)smem_bytes);
    gfusedmax_kernel<<<B, THREADS, smem_bytes>>>(x, A, out);
}